// round 10
// baseline (speedup 1.0000x reference)
#include <cuda_runtime.h>

// Schroeder reverb: 4 series allpass + 4 parallel feedback combs, T=131072, W=128 fp32.
//
// Lever that works on this codegen: thread count (ptxas caps per-thread MLP~2
// no matter how loads are batched). R8: P=64 -> DRAM 40%. R9: P=32 -> DRAM
// 47.5%, occ 36%. R10 (this): allpass P=16/H=24 (~280k threads/stage,
// restart err 0.7^24=1.9e-4 -> final ~6e-5, threshold 1e-3), combs P=32
// with EXACT full-prefix warm-up (threads x2, no approximation).
//
// Chain semantics (matches the jnp block-scan):
//   allpass: y[k] = -g*y[k-1] + x[k] + g*x[k-1],  y[0] = 0 (x[0] enters history)
//   comb:    y[k] =  g*y[k-1] + x[k],             y[0] = 0

#define TT 131072
#define W4 32
#define AP_P 16        // allpass payload steps per segment
#define AP_H 24        // allpass warm-up steps (0.7^24 ~ 1.9e-4)
#define CB_P 32        // comb payload steps per segment (warm-up = full prefix, exact)
#define BATCH 8

__device__ float4 g_scratchA[TT * W4];   // 64 MB
__device__ float4 g_scratchB[TT * W4];   // 64 MB

__device__ __forceinline__ float4 ldg_nc4(const float4* p) {
    float4 v;
    asm volatile("ld.global.nc.v4.f32 {%0,%1,%2,%3}, [%4];"
                 : "=f"(v.x), "=f"(v.y), "=f"(v.z), "=f"(v.w)
                 : "l"(p));
    return v;
}

__device__ __forceinline__ float4 ap_step(float g, float4 xp, float4 yp, float4 xk) {
    float4 y;
    y.x = fmaf(g, xp.x - yp.x, xk.x);
    y.y = fmaf(g, xp.y - yp.y, xk.y);
    y.z = fmaf(g, xp.z - yp.z, xk.z);
    y.w = fmaf(g, xp.w - yp.w, xk.w);
    return y;
}

// Segmented allpass stage, out-of-place (in != out guaranteed).
__global__ void __launch_bounds__(128) allpass_seg_kernel(
    const float4* __restrict__ in, float4* __restrict__ out,
    int N, int nseg, float g)
{
    const int tid = blockIdx.x * 128 + threadIdx.x;
    if (tid >= 32 * N * nseg) return;
    const int v   = tid & 31;
    const int rn  = tid >> 5;
    const int r   = rn % N;
    const int seg = rn / N;

    const int len = (TT - 1 - r) / N + 1;
    const int kbp = seg * AP_P;             // payload begin
    if (kbp >= len) return;
    const int kend = min(len, kbp + AP_P);  // payload end (exclusive)
    const int kw = (kbp > AP_H) ? (kbp - AP_H) : 0;

    const int stride = N * W4;
    float4 xprev, yprev = make_float4(0.f, 0.f, 0.f, 0.f);
    int k;
    if (kw == 0) {
        const int idx0 = r * W4 + v;
        xprev = ldg_nc4(in + idx0);          // k=0: x enters history, y=0
        if (seg == 0) out[idx0] = make_float4(0.f, 0.f, 0.f, 0.f);
        k = 1;
    } else {
        xprev = ldg_nc4(in + (kw - 1) * stride + r * W4 + v);
        k = kw;
    }

    int idx = k * stride + r * W4 + v;
    const int kp = (kbp > 1) ? kbp : 1;

    // warm-up: state only
    while (k + BATCH <= kp) {
        float4 xs[BATCH];
#pragma unroll
        for (int j = 0; j < BATCH; j++) xs[j] = ldg_nc4(in + idx + j * stride);
#pragma unroll
        for (int j = 0; j < BATCH; j++) {
            yprev = ap_step(g, xprev, yprev, xs[j]);
            xprev = xs[j];
        }
        idx += BATCH * stride; k += BATCH;
    }
    for (; k < kp; ++k, idx += stride) {
        float4 xk = ldg_nc4(in + idx);
        yprev = ap_step(g, xprev, yprev, xk);
        xprev = xk;
    }

    // payload: compute + store
    while (k + BATCH <= kend) {
        float4 xs[BATCH];
#pragma unroll
        for (int j = 0; j < BATCH; j++) xs[j] = ldg_nc4(in + idx + j * stride);
#pragma unroll
        for (int j = 0; j < BATCH; j++) {
            float4 y = ap_step(g, xprev, yprev, xs[j]);
            out[idx + j * stride] = y;
            xprev = xs[j];
            yprev = y;
        }
        idx += BATCH * stride; k += BATCH;
    }
    for (; k < kend; ++k, idx += stride) {
        float4 xk = ldg_nc4(in + idx);
        float4 y = ap_step(g, xprev, yprev, xk);
        out[idx] = y;
        xprev = xk;
        yprev = y;
    }
}

// Segmented feedback comb with EXACT warm-up: every segment replays the chain
// from k=0 (chain len <= 118, so warm-up <= 96 steps). Bit-exact.
// MODE 0: plain store (first comb; also clears 0xAA poison).
// MODE 1: same-thread vector RMW accumulate (kernels serialize -> deterministic).
template <int MODE>
__global__ void __launch_bounds__(128) comb_kernel(
    const float4* __restrict__ in, float4* out, int N, int nseg, float g)
{
    const int tid = blockIdx.x * 128 + threadIdx.x;
    if (tid >= 32 * N * nseg) return;
    const int v   = tid & 31;
    const int rn  = tid >> 5;
    const int r   = rn % N;
    const int seg = rn / N;

    const int len = (TT - 1 - r) / N + 1;
    const int kbp = seg * CB_P;
    if (kbp >= len) return;
    const int kend = min(len, kbp + CB_P);

    const int stride = N * W4;
    float4 yprev = make_float4(0.f, 0.f, 0.f, 0.f);
    int k = 1;                                   // exact: start at chain head
    if (seg == 0 && MODE == 0)
        out[r * W4 + v] = make_float4(0.f, 0.f, 0.f, 0.f);   // y[0] = 0

    int idx = stride + r * W4 + v;               // k = 1
    const int kp = (kbp > 1) ? kbp : 1;

    // warm-up: state only (full prefix -> exact)
    while (k + BATCH <= kp) {
        float4 xs[BATCH];
#pragma unroll
        for (int j = 0; j < BATCH; j++) xs[j] = ldg_nc4(in + idx + j * stride);
#pragma unroll
        for (int j = 0; j < BATCH; j++) {
            yprev.x = fmaf(g, yprev.x, xs[j].x);
            yprev.y = fmaf(g, yprev.y, xs[j].y);
            yprev.z = fmaf(g, yprev.z, xs[j].z);
            yprev.w = fmaf(g, yprev.w, xs[j].w);
        }
        idx += BATCH * stride; k += BATCH;
    }
    for (; k < kp; ++k, idx += stride) {
        float4 xk = ldg_nc4(in + idx);
        yprev.x = fmaf(g, yprev.x, xk.x);
        yprev.y = fmaf(g, yprev.y, xk.y);
        yprev.z = fmaf(g, yprev.z, xk.z);
        yprev.w = fmaf(g, yprev.w, xk.w);
    }

    // payload
    while (k + BATCH <= kend) {
        float4 xs[BATCH];
#pragma unroll
        for (int j = 0; j < BATCH; j++) xs[j] = ldg_nc4(in + idx + j * stride);
        float4 os[BATCH];
        if (MODE == 1) {
#pragma unroll
            for (int j = 0; j < BATCH; j++) os[j] = out[idx + j * stride];
        }
#pragma unroll
        for (int j = 0; j < BATCH; j++) {
            float4 y;
            y.x = fmaf(g, yprev.x, xs[j].x);
            y.y = fmaf(g, yprev.y, xs[j].y);
            y.z = fmaf(g, yprev.z, xs[j].z);
            y.w = fmaf(g, yprev.w, xs[j].w);
            if (MODE == 0) {
                out[idx + j * stride] = y;
            } else {
                float4 o = os[j];
                o.x += y.x; o.y += y.y; o.z += y.z; o.w += y.w;
                out[idx + j * stride] = o;
            }
            yprev = y;
        }
        idx += BATCH * stride; k += BATCH;
    }
    for (; k < kend; ++k, idx += stride) {
        float4 xk = ldg_nc4(in + idx);
        float4 y;
        y.x = fmaf(g, yprev.x, xk.x);
        y.y = fmaf(g, yprev.y, xk.y);
        y.z = fmaf(g, yprev.z, xk.z);
        y.w = fmaf(g, yprev.w, xk.w);
        if (MODE == 0) {
            out[idx] = y;
        } else {
            float4 o = out[idx];
            o.x += y.x; o.y += y.y; o.z += y.z; o.w += y.w;
            out[idx] = o;
        }
        yprev = y;
    }
}

static inline int grid_of(int N, int nseg) { return (32 * N * nseg + 127) / 128; }
static inline int nseg_ap(int N) { int L = (TT - 1) / N + 1; return (L + AP_P - 1) / AP_P; }
static inline int nseg_cb(int N) { int L = (TT - 1) / N + 1; return (L + CB_P - 1) / CB_P; }

extern "C" void kernel_launch(void* const* d_in, const int* in_sizes, int n_in,
                              void* d_out, int out_size)
{
    const float4* x = (const float4*)d_in[0];
    float4* out = (float4*)d_out;

    float4 *A, *B;
    cudaGetSymbolAddress((void**)&A, g_scratchA);
    cudaGetSymbolAddress((void**)&B, g_scratchB);

    // Series allpass chain, ping-pong out-of-place; every stage fully rewrites
    // its destination -> graph replays deterministic.
    { int N = 225, s = nseg_ap(N); allpass_seg_kernel<<<grid_of(N, s), 128>>>(x, A, N, s, 0.7f); }
    { int N = 556, s = nseg_ap(N); allpass_seg_kernel<<<grid_of(N, s), 128>>>(A, B, N, s, 0.7f); }
    { int N = 441, s = nseg_ap(N); allpass_seg_kernel<<<grid_of(N, s), 128>>>(B, A, N, s, 0.7f); }
    { int N = 341, s = nseg_ap(N); allpass_seg_kernel<<<grid_of(N, s), 128>>>(A, B, N, s, 0.7f); }

    // Parallel comb bank summed into d_out.
    { int N = 1116, s = nseg_cb(N); comb_kernel<0><<<grid_of(N, s), 128>>>(B, out, N, s, 0.84f); }
    { int N = 1188, s = nseg_cb(N); comb_kernel<1><<<grid_of(N, s), 128>>>(B, out, N, s, 0.82f); }
    { int N = 1277, s = nseg_cb(N); comb_kernel<1><<<grid_of(N, s), 128>>>(B, out, N, s, 0.80f); }
    { int N = 1356, s = nseg_cb(N); comb_kernel<1><<<grid_of(N, s), 128>>>(B, out, N, s, 0.78f); }
}

// round 11
// speedup vs baseline: 1.0496x; 1.0496x over previous
#include <cuda_runtime.h>

// Schroeder reverb: 4 series allpass + 4 parallel feedback combs, T=131072, W=128 fp32.
//
// R10 post-mortem: concurrency exhausted (occ 72% made it slower); ping-pong
// A+B=128MB > 126MB L2 kept ~55% of stage reads on HBM. R11: ONE 64MB scratch,
// allpass stages IN-PLACE via (state, payload) kernel pairs:
//   - state kernel (read-only) computes each segment's warm-up restart state
//     (H=24 steps from zero y; 0.7^24~1.9e-4, final ~9e-5 measured at R10)
//     into a small side array.
//   - payload kernel touches each element exactly once, read-before-write in
//     the SAME thread; store value depends on the load -> order enforced by
//     data dependency. The one non-dependent store (y[0]=0 vs x[0] load) uses
//     an asm-ordered load ("memory" clobber) — R1 aliasing-bug class closed.
// Working set for stages 2-4 = 64MB -> fully L2-resident; combs then read an
// L2-resident S. Combs unchanged from R10 (P=32, exact full-prefix warm-up).
//
// Chain semantics (matches the jnp block-scan):
//   allpass: y[k] = -g*y[k-1] + x[k] + g*x[k-1],  y[0] = 0 (x[0] enters history)
//   comb:    y[k] =  g*y[k-1] + x[k],             y[0] = 0

#define TT 131072
#define W4 32
#define AP_P 32        // allpass payload steps per segment (R9 optimum)
#define AP_H 24        // allpass warm-up steps
#define CB_P 32        // comb payload steps (warm-up = full prefix, exact)
#define BATCH 8
#define MAXRN 4608     // max (seg*N+r) slots across stages (<=4448 needed)

__device__ float4 g_scratch[TT * W4];      // 64 MB single scratch
__device__ float4 g_stateX[MAXRN * 32];    // 2.4 MB restart xprev
__device__ float4 g_stateY[MAXRN * 32];    // 2.4 MB restart yprev

__device__ __forceinline__ float4 ldg_nc4(const float4* p) {
    float4 v;
    asm volatile("ld.global.nc.v4.f32 {%0,%1,%2,%3}, [%4];"
                 : "=f"(v.x), "=f"(v.y), "=f"(v.z), "=f"(v.w)
                 : "l"(p));
    return v;
}

// Ordered load: "memory" clobber pins subsequent same-address stores after it.
__device__ __forceinline__ float4 ld4_ordered(const float4* p) {
    float4 v;
    asm volatile("ld.global.v4.f32 {%0,%1,%2,%3}, [%4];"
                 : "=f"(v.x), "=f"(v.y), "=f"(v.z), "=f"(v.w)
                 : "l"(p) : "memory");
    return v;
}

__device__ __forceinline__ float4 ap_step(float g, float4 xp, float4 yp, float4 xk) {
    float4 y;
    y.x = fmaf(g, xp.x - yp.x, xk.x);
    y.y = fmaf(g, xp.y - yp.y, xk.y);
    y.z = fmaf(g, xp.z - yp.z, xk.z);
    y.w = fmaf(g, xp.w - yp.w, xk.w);
    return y;
}

// ---- allpass state kernel: read-only; computes (xprev,yprev) at each payload
// ---- start kbp = seg*AP_P (seg>=1) by running H warm-up steps from zero y.
__global__ void __launch_bounds__(128) ap_state_kernel(
    const float4* __restrict__ in, int N, int nseg, float g)
{
    const int tid = blockIdx.x * 128 + threadIdx.x;
    if (tid >= 32 * N * nseg) return;
    const int v   = tid & 31;
    const int rn  = tid >> 5;
    const int r   = rn % N;
    const int seg = rn / N;
    if (seg == 0) return;                         // seg 0 starts exact at head

    const int len = (TT - 1 - r) / N + 1;
    const int kbp = seg * AP_P;
    if (kbp >= len) return;
    const int kw = kbp - AP_H;                    // >= AP_P - AP_H = 8 > 0

    const int stride = N * W4;
    const int base = r * W4 + v;
    float4 xprev = ldg_nc4(in + (kw - 1) * stride + base);
    float4 yprev = make_float4(0.f, 0.f, 0.f, 0.f);

    int idx = kw * stride + base;
    int k = kw;
    while (k + BATCH <= kbp) {
        float4 xs[BATCH];
#pragma unroll
        for (int j = 0; j < BATCH; j++) xs[j] = ldg_nc4(in + idx + j * stride);
#pragma unroll
        for (int j = 0; j < BATCH; j++) {
            yprev = ap_step(g, xprev, yprev, xs[j]);
            xprev = xs[j];
        }
        idx += BATCH * stride; k += BATCH;
    }
    for (; k < kbp; ++k, idx += stride) {
        float4 xk = ldg_nc4(in + idx);
        yprev = ap_step(g, xprev, yprev, xk);
        xprev = xk;
    }
    g_stateX[rn * 32 + v] = xprev;
    g_stateY[rn * 32 + v] = yprev;
}

// ---- allpass payload kernel: may run IN-PLACE (in == out). Each element is
// ---- read then written by the same thread; stores depend on loads.
__global__ void __launch_bounds__(128) ap_payload_kernel(
    const float4* in, float4* out, int N, int nseg, float g)
{
    const int tid = blockIdx.x * 128 + threadIdx.x;
    if (tid >= 32 * N * nseg) return;
    const int v   = tid & 31;
    const int rn  = tid >> 5;
    const int r   = rn % N;
    const int seg = rn / N;

    const int len = (TT - 1 - r) / N + 1;
    const int kbp = seg * AP_P;
    if (kbp >= len) return;
    const int kend = min(len, kbp + AP_P);

    const int stride = N * W4;
    const int base = r * W4 + v;

    float4 xprev, yprev;
    int k;
    if (seg == 0) {
        xprev = ld4_ordered(in + base);           // ordered: read x[0] BEFORE
        out[base] = make_float4(0.f, 0.f, 0.f, 0.f);  // overwriting y[0]=0
        yprev = make_float4(0.f, 0.f, 0.f, 0.f);
        k = 1;
    } else {
        xprev = g_stateX[rn * 32 + v];
        yprev = g_stateY[rn * 32 + v];
        k = kbp;
    }

    int idx = k * stride + base;
    while (k + BATCH <= kend) {
        float4 xs[BATCH];
#pragma unroll
        for (int j = 0; j < BATCH; j++) xs[j] = ldg_nc4(in + idx + j * stride);
#pragma unroll
        for (int j = 0; j < BATCH; j++) {
            float4 y = ap_step(g, xprev, yprev, xs[j]);
            out[idx + j * stride] = y;            // depends on xs[j] -> ordered
            xprev = xs[j];
            yprev = y;
        }
        idx += BATCH * stride; k += BATCH;
    }
    for (; k < kend; ++k, idx += stride) {
        float4 xk = ldg_nc4(in + idx);
        float4 y = ap_step(g, xprev, yprev, xk);
        out[idx] = y;
        xprev = xk;
        yprev = y;
    }
}

// ---- segmented feedback comb, EXACT full-prefix warm-up (chain len <= 118).
// MODE 0: plain store (first comb; also clears 0xAA poison).
// MODE 1: same-thread vector RMW accumulate (kernels serialize -> deterministic).
template <int MODE>
__global__ void __launch_bounds__(128) comb_kernel(
    const float4* __restrict__ in, float4* out, int N, int nseg, float g)
{
    const int tid = blockIdx.x * 128 + threadIdx.x;
    if (tid >= 32 * N * nseg) return;
    const int v   = tid & 31;
    const int rn  = tid >> 5;
    const int r   = rn % N;
    const int seg = rn / N;

    const int len = (TT - 1 - r) / N + 1;
    const int kbp = seg * CB_P;
    if (kbp >= len) return;
    const int kend = min(len, kbp + CB_P);

    const int stride = N * W4;
    float4 yprev = make_float4(0.f, 0.f, 0.f, 0.f);
    int k = 1;                                    // exact: replay from head
    if (seg == 0 && MODE == 0)
        out[r * W4 + v] = make_float4(0.f, 0.f, 0.f, 0.f);   // y[0] = 0

    int idx = stride + r * W4 + v;
    const int kp = (kbp > 1) ? kbp : 1;

    while (k + BATCH <= kp) {
        float4 xs[BATCH];
#pragma unroll
        for (int j = 0; j < BATCH; j++) xs[j] = ldg_nc4(in + idx + j * stride);
#pragma unroll
        for (int j = 0; j < BATCH; j++) {
            yprev.x = fmaf(g, yprev.x, xs[j].x);
            yprev.y = fmaf(g, yprev.y, xs[j].y);
            yprev.z = fmaf(g, yprev.z, xs[j].z);
            yprev.w = fmaf(g, yprev.w, xs[j].w);
        }
        idx += BATCH * stride; k += BATCH;
    }
    for (; k < kp; ++k, idx += stride) {
        float4 xk = ldg_nc4(in + idx);
        yprev.x = fmaf(g, yprev.x, xk.x);
        yprev.y = fmaf(g, yprev.y, xk.y);
        yprev.z = fmaf(g, yprev.z, xk.z);
        yprev.w = fmaf(g, yprev.w, xk.w);
    }

    while (k + BATCH <= kend) {
        float4 xs[BATCH];
#pragma unroll
        for (int j = 0; j < BATCH; j++) xs[j] = ldg_nc4(in + idx + j * stride);
        float4 os[BATCH];
        if (MODE == 1) {
#pragma unroll
            for (int j = 0; j < BATCH; j++) os[j] = out[idx + j * stride];
        }
#pragma unroll
        for (int j = 0; j < BATCH; j++) {
            float4 y;
            y.x = fmaf(g, yprev.x, xs[j].x);
            y.y = fmaf(g, yprev.y, xs[j].y);
            y.z = fmaf(g, yprev.z, xs[j].z);
            y.w = fmaf(g, yprev.w, xs[j].w);
            if (MODE == 0) {
                out[idx + j * stride] = y;
            } else {
                float4 o = os[j];
                o.x += y.x; o.y += y.y; o.z += y.z; o.w += y.w;
                out[idx + j * stride] = o;
            }
            yprev = y;
        }
        idx += BATCH * stride; k += BATCH;
    }
    for (; k < kend; ++k, idx += stride) {
        float4 xk = ldg_nc4(in + idx);
        float4 y;
        y.x = fmaf(g, yprev.x, xk.x);
        y.y = fmaf(g, yprev.y, xk.y);
        y.z = fmaf(g, yprev.z, xk.z);
        y.w = fmaf(g, yprev.w, xk.w);
        if (MODE == 0) {
            out[idx] = y;
        } else {
            float4 o = out[idx];
            o.x += y.x; o.y += y.y; o.z += y.z; o.w += y.w;
            out[idx] = o;
        }
        yprev = y;
    }
}

static inline int grid_of(int N, int nseg) { return (32 * N * nseg + 127) / 128; }
static inline int nseg_ap(int N) { int L = (TT - 1) / N + 1; return (L + AP_P - 1) / AP_P; }
static inline int nseg_cb(int N) { int L = (TT - 1) / N + 1; return (L + CB_P - 1) / CB_P; }

extern "C" void kernel_launch(void* const* d_in, const int* in_sizes, int n_in,
                              void* d_out, int out_size)
{
    const float4* x = (const float4*)d_in[0];
    float4* out = (float4*)d_out;

    float4* S;
    cudaGetSymbolAddress((void**)&S, g_scratch);

    // Series allpass chain. Stage 1: x -> S (out-of-place). Stages 2-4:
    // in-place on S (state kernel reads warm-up regions BEFORE the payload
    // kernel overwrites them; launches serialize on the stream).
    // Every payload fully rewrites its destination -> deterministic replays.
    { int N = 225, s = nseg_ap(N);
      ap_state_kernel  <<<grid_of(N, s), 128>>>(x, N, s, 0.7f);
      ap_payload_kernel<<<grid_of(N, s), 128>>>(x, S, N, s, 0.7f); }
    { int N = 556, s = nseg_ap(N);
      ap_state_kernel  <<<grid_of(N, s), 128>>>(S, N, s, 0.7f);
      ap_payload_kernel<<<grid_of(N, s), 128>>>(S, S, N, s, 0.7f); }
    { int N = 441, s = nseg_ap(N);
      ap_state_kernel  <<<grid_of(N, s), 128>>>(S, N, s, 0.7f);
      ap_payload_kernel<<<grid_of(N, s), 128>>>(S, S, N, s, 0.7f); }
    { int N = 341, s = nseg_ap(N);
      ap_state_kernel  <<<grid_of(N, s), 128>>>(S, N, s, 0.7f);
      ap_payload_kernel<<<grid_of(N, s), 128>>>(S, S, N, s, 0.7f); }

    // Parallel comb bank summed into d_out; S is now L2-resident.
    { int N = 1116, s = nseg_cb(N); comb_kernel<0><<<grid_of(N, s), 128>>>(S, out, N, s, 0.84f); }
    { int N = 1188, s = nseg_cb(N); comb_kernel<1><<<grid_of(N, s), 128>>>(S, out, N, s, 0.82f); }
    { int N = 1277, s = nseg_cb(N); comb_kernel<1><<<grid_of(N, s), 128>>>(S, out, N, s, 0.80f); }
    { int N = 1356, s = nseg_cb(N); comb_kernel<1><<<grid_of(N, s), 128>>>(S, out, N, s, 0.78f); }
}